// round 11
// baseline (speedup 1.0000x reference)
#include <cuda_runtime.h>
#include <cstddef>

#define Hd    50
#define WP    52          // xgemm weight row stride (floats)
#define G4    200
#define Bsz   4096
#define Tt    256
#define TBtot (Tt*Bsz)    // 1048576
#define NCHUNK (TBtot/32) // 32768
#define RNT   512         // rec threads (16 warps)
#define EPG   14          // rec: elements per group
#define EPCTA 28          // rec: elements per CTA (2 groups)
#define RGRID ((Bsz + EPCTA - 1) / EPCTA)   // 147 CTAs

typedef unsigned long long ull;

// Inter-layer activations [tb][50] + precomputed input-side preacts [tb][200]
__device__ float g_ysA[(size_t)TBtot * Hd];
__device__ float g_ysB[(size_t)TBtot * Hd];
__device__ float g_xg[(size_t)TBtot * 200];

__device__ __forceinline__ ull ffma2(ull a, ull b, ull c) {
    ull d;
    asm("fma.rn.f32x2 %0, %1, %2, %3;" : "=l"(d) : "l"(a), "l"(b), "l"(c));
    return d;
}
__device__ __forceinline__ ull addf2(ull a, ull b) {
    ull d;
    asm("add.rn.f32x2 %0, %1, %2;" : "=l"(d) : "l"(a), "l"(b));
    return d;
}
__device__ __forceinline__ float f2sum(ull v) {
    float lo, hi;
    asm("mov.b64 {%0, %1}, %2;" : "=f"(lo), "=f"(hi) : "l"(v));
    return lo + hi;
}
__device__ __forceinline__ float sigf(float x) {
    return __fdividef(1.0f, 1.0f + __expf(-x));
}
__device__ __forceinline__ float tanhf_fast(float x) {
    return 1.0f - __fdividef(2.0f, __expf(2.0f * x) + 1.0f);
}

// ---------------- Phase A, layer 0: XG = x * w_ih0^T + b0 (rank-1) -------------
__global__ __launch_bounds__(200) void xg0_kernel(const float* __restrict__ x,
                                                  const float* __restrict__ w0,
                                                  const float* __restrict__ b0)
{
    __shared__ float xs[32];
    const int cid = blockIdx.x;
    const int t   = cid >> 7;
    const int bb  = (cid & 127) << 5;
    const int row = threadIdx.x;           // 0..199
    if (row < 32) xs[row] = x[(size_t)(bb + row) * Tt + t];
    const float wv = w0[row], bv = b0[row];
    __syncthreads();
    float* base = g_xg + ((size_t)t * Bsz + bb) * 200 + row;
    #pragma unroll 8
    for (int el = 0; el < 32; el++)
        base[(size_t)el * 200] = xs[el] * wv + bv;
}

// ---------------- Phase A, layers 1..4: XG = ys * W_ih^T + bias ----------------
// 256 threads = 8 warps; warp wg owns rows [25wg,25wg+25) in regs (lane=row).
// Double-buffered staging, ONE barrier per chunk, 4-el unrolled compute.
__global__ __launch_bounds__(256, 2) void xgemm_kernel(const float* __restrict__ ys,
                                                       const float* __restrict__ w,
                                                       const float* __restrict__ bias)
{
    __shared__ float sin[2][32 * WP];
    const int tid  = threadIdx.x;
    const int wid  = tid >> 5;
    const int lane = tid & 31;
    const bool act = lane < 25;
    const int row  = 25 * wid + (act ? lane : 24);

    ull wreg[25];
    {
        const ull* wp = (const ull*)(w + row * Hd);
        #pragma unroll
        for (int q = 0; q < 25; q++) wreg[q] = wp[q];
    }
    const float br = bias[row];

    const int stride = gridDim.x;
    int c = blockIdx.x;
    float pf[7];

    // prologue: chunk c -> sin[0]; prefetch chunk c+stride into pf
    #pragma unroll
    for (int k = 0; k < 7; k++) {
        int idx = tid + 256 * k;
        pf[k] = (idx < 1600) ? ys[(size_t)c * 1600 + idx] : 0.0f;
    }
    #pragma unroll
    for (int k = 0; k < 7; k++) {
        int idx = tid + 256 * k;
        if (idx < 1600) { int el = idx / 50, j = idx - el * 50; sin[0][el * WP + j] = pf[k]; }
    }
    if (c + stride < NCHUNK) {
        #pragma unroll
        for (int k = 0; k < 7; k++) {
            int idx = tid + 256 * k;
            if (idx < 1600) pf[k] = ys[(size_t)(c + stride) * 1600 + idx];
        }
    }
    __syncthreads();

    int buf = 0;
    for (; c < NCHUNK; c += stride) {
        // stage chunk c+stride into the other buffer (data already in pf)
        if (c + stride < NCHUNK) {
            #pragma unroll
            for (int k = 0; k < 7; k++) {
                int idx = tid + 256 * k;
                if (idx < 1600) { int el = idx / 50, j = idx - el * 50; sin[buf ^ 1][el * WP + j] = pf[k]; }
            }
        }
        // prefetch chunk c+2*stride
        if (c + 2 * stride < NCHUNK) {
            #pragma unroll
            for (int k = 0; k < 7; k++) {
                int idx = tid + 256 * k;
                if (idx < 1600) pf[k] = ys[(size_t)(c + 2 * stride) * 1600 + idx];
            }
        }

        // compute chunk c from sin[buf]: 8 x 4-el groups, 4 independent chains
        const float* sb = sin[buf];
        float* obase = g_xg + ((size_t)c * 32) * 200 + row;
        #pragma unroll
        for (int el = 0; el < 32; el += 4) {
            const ulonglong2* h0 = (const ulonglong2*)(sb + (el + 0) * WP);
            const ulonglong2* h1 = (const ulonglong2*)(sb + (el + 1) * WP);
            const ulonglong2* h2 = (const ulonglong2*)(sb + (el + 2) * WP);
            const ulonglong2* h3 = (const ulonglong2*)(sb + (el + 3) * WP);
            ull a0 = 0ull, a1 = 0ull, a2 = 0ull, a3 = 0ull;
            #pragma unroll
            for (int q = 0; q < 12; q++) {
                ulonglong2 v0 = h0[q], v1 = h1[q], v2 = h2[q], v3 = h3[q];
                a0 = ffma2(wreg[2*q], v0.x, a0); a0 = ffma2(wreg[2*q+1], v0.y, a0);
                a1 = ffma2(wreg[2*q], v1.x, a1); a1 = ffma2(wreg[2*q+1], v1.y, a1);
                a2 = ffma2(wreg[2*q], v2.x, a2); a2 = ffma2(wreg[2*q+1], v2.y, a2);
                a3 = ffma2(wreg[2*q], v3.x, a3); a3 = ffma2(wreg[2*q+1], v3.y, a3);
            }
            a0 = ffma2(wreg[24], ((const ull*)h0)[24], a0);
            a1 = ffma2(wreg[24], ((const ull*)h1)[24], a1);
            a2 = ffma2(wreg[24], ((const ull*)h2)[24], a2);
            a3 = ffma2(wreg[24], ((const ull*)h3)[24], a3);
            if (act) {
                obase[(size_t)(el + 0) * 200] = f2sum(a0) + br;
                obase[(size_t)(el + 1) * 200] = f2sum(a1) + br;
                obase[(size_t)(el + 2) * 200] = f2sum(a2) + br;
                obase[(size_t)(el + 3) * 200] = f2sum(a3) + br;
            }
        }
        __syncthreads();   // sin[buf^1] staged AND all readers of sin[buf] done
        buf ^= 1;
    }
}

// ---------------- Phase B: recurrence, weights register-stationary -------------
// 16 warps = 2 groups x 8 warps; group owns EPG=14 batch elements (CTA=28).
// grid 147 -> every SM busy. Split accumulators (2 chains/el) for FMA ILP.
__global__ __launch_bounds__(RNT, 1)
void rec_kernel(const float* __restrict__ w_hh,
                float* __restrict__ ys_out,
                const float* __restrict__ fc_w,
                const float* __restrict__ fc_b,
                float* __restrict__ out)
{
    __shared__ float hbuf[EPCTA][52];    // [ei][u], cols 50,51 stay 0
    __shared__ float pbuf[EPCTA][208];   // [ei][row]

    const int tid  = threadIdx.x;
    const int wid  = tid >> 5;
    const int lane = tid & 31;
    const int g    = wid >> 3;        // group 0..1
    const int wg   = wid & 7;         // warp-in-group 0..7
    const int tidg = tid & 255;       // thread-in-group
    const int barid = 1 + g;

    const int bG = blockIdx.x * EPCTA + g * EPG;   // group's first element

    // ---- weights: lane<25 owns row 25wg+lane (kept in 50 regs) ----
    const bool wact = lane < 25;
    const int myrow = 25 * wg + (wact ? lane : 24);
    ull wreg[25];
    {
        const ull* wp = (const ull*)(w_hh + myrow * Hd);
        #pragma unroll
        for (int q = 0; q < 25; q++) wreg[q] = wp[q];
    }

    // ---- gates items: 3 fixed (el,u) per thread (700 items over 256 threads) ----
    int elk[3], uk[3];
    bool actk[3], gbl[3];
    #pragma unroll
    for (int k = 0; k < 3; k++) {
        int item = tidg + 256 * k;
        actk[k] = item < EPG * 50;
        int it = actk[k] ? item : (EPG * 50 - 1);
        elk[k] = it / 50;
        uk[k]  = it - elk[k] * 50;
        gbl[k] = actk[k] && (bG + elk[k] < Bsz);
    }
    float c[3] = {0.f, 0.f, 0.f};

    // ---- zero hbuf ----
    for (int i = tid; i < EPCTA * 52; i += RNT) ((float*)hbuf)[i] = 0.0f;
    __syncthreads();

    for (int t = 0; t < Tt; t++) {
        const size_t tb = (size_t)t * Bsz;

        // ---- XG prefetch for my gate items (guarded, hidden under dot) ----
        float xgr[3][4];
        #pragma unroll
        for (int k = 0; k < 3; k++) {
            if (gbl[k]) {
                const float* xp = g_xg + (tb + bG + elk[k]) * 200 + uk[k];
                #pragma unroll
                for (int gg = 0; gg < 4; gg++) xgr[k][gg] = xp[gg * 50];
            } else {
                #pragma unroll
                for (int gg = 0; gg < 4; gg++) xgr[k][gg] = 0.0f;
            }
        }

        // ---- dot: stream EPG elements; 2 acc chains per el ----
        #pragma unroll 2
        for (int el = 0; el < EPG; el++) {
            const int ei = g * EPG + el;
            ulonglong2 hv[13];
            {
                const ulonglong2* hp = (const ulonglong2*)hbuf[ei];
                #pragma unroll
                for (int q = 0; q < 13; q++) hv[q] = hp[q];
            }
            ull alo = 0ull, ahi = 0ull;
            #pragma unroll
            for (int q = 0; q < 6; q++) {
                alo = ffma2(wreg[2*q],   hv[q].x, alo);
                alo = ffma2(wreg[2*q+1], hv[q].y, alo);
            }
            #pragma unroll
            for (int q = 6; q < 12; q++) {
                ahi = ffma2(wreg[2*q],   hv[q].x, ahi);
                ahi = ffma2(wreg[2*q+1], hv[q].y, ahi);
            }
            ahi = ffma2(wreg[24], hv[12].x, ahi);
            if (wact) pbuf[ei][25 * wg + lane] = f2sum(addf2(alo, ahi));
        }

        asm volatile("bar.sync %0, %1;" :: "r"(barid), "r"(256) : "memory");

        // ---- gates: 700 items over 256 group threads ----
        #pragma unroll
        for (int k = 0; k < 3; k++) {
            if (actk[k]) {
                const int ei = g * EPG + elk[k];
                const int u  = uk[k];
                float pi = pbuf[ei][u]        + xgr[k][0];
                float pf = pbuf[ei][50 + u]   + xgr[k][1];
                float pg = pbuf[ei][100 + u]  + xgr[k][2];
                float po = pbuf[ei][150 + u]  + xgr[k][3];
                c[k] = sigf(pf) * c[k] + sigf(pi) * tanhf_fast(pg);
                float hv = sigf(po) * tanhf_fast(c[k]);
                hbuf[ei][u] = hv;
                if (gbl[k] && ys_out) ys_out[(tb + bG + elk[k]) * Hd + u] = hv;
            }
        }

        asm volatile("bar.sync %0, %1;" :: "r"(barid), "r"(256) : "memory");
    }

    // ---- FC head (last layer only) ----
    if (out != nullptr) {
        __syncthreads();
        int be = blockIdx.x * EPCTA + tid;
        if (tid < EPCTA && be < Bsz) {
            float sres = fc_b[0];
            #pragma unroll 10
            for (int j = 0; j < Hd; j++) sres += hbuf[tid][j] * fc_w[j];
            out[be] = sres;
        }
    }
}

extern "C" void kernel_launch(void* const* d_in, const int* in_sizes, int n_in,
                              void* d_out, int out_size)
{
    const float* x     = (const float*)d_in[0];  // [B,T,1]
    const float* w_ih0 = (const float*)d_in[1];  // [200,1]
    const float* w_hh0 = (const float*)d_in[2];  // [200,50]
    const float* b0    = (const float*)d_in[3];  // [200]
    const float* w_ih  = (const float*)d_in[4];  // [4,200,50]
    const float* w_hh  = (const float*)d_in[5];  // [4,200,50]
    const float* b     = (const float*)d_in[6];  // [4,200]
    const float* fc_w  = (const float*)d_in[7];  // [1,50]
    const float* fc_b  = (const float*)d_in[8];  // [1]
    float* out = (float*)d_out;

    float *ysA = nullptr, *ysB = nullptr;
    cudaGetSymbolAddress((void**)&ysA, g_ysA);
    cudaGetSymbolAddress((void**)&ysB, g_ysB);

    // Layer 0
    xg0_kernel<<<NCHUNK, 200>>>(x, w_ih0, b0);
    rec_kernel<<<RGRID, RNT>>>(w_hh0, ysA, nullptr, nullptr, nullptr);

    // Layers 1..3
    const float* src = ysA;
    float* dst = ysB;
    for (int l = 0; l < 3; l++) {
        xgemm_kernel<<<296, 256>>>(src, w_ih + (size_t)l * G4 * Hd, b + (size_t)l * G4);
        rec_kernel<<<RGRID, RNT>>>(w_hh + (size_t)l * G4 * Hd, dst, nullptr, nullptr, nullptr);
        const float* tmp = dst; dst = (float*)src; src = tmp;
    }

    // Layer 4: fused FC head
    xgemm_kernel<<<296, 256>>>(src, w_ih + (size_t)3 * G4 * Hd, b + (size_t)3 * G4);
    rec_kernel<<<RGRID, RNT>>>(w_hh + (size_t)3 * G4 * Hd, nullptr, fc_w, fc_b, out);
}